// round 2
// baseline (speedup 1.0000x reference)
#include <cuda_runtime.h>
#include <cstdint>

// ---------------- problem constants ----------------
#define GGRP   8
#define DDISP  64
#define EDIM   128
#define K1DIM  72            // G*9
#define MTOT   409600        // N*NS
#define TILE_M 128
#define NTILES 3200          // MTOT / TILE_M
#define GRID_X 152
#define NTHR   256           // 8 warps
#define EMB_ELEMS 52428800   // MTOT*EDIM
#define TOT_ELEMS 52838400   // + MTOT

// ---------------- smem layout (byte offsets) ----------------
// strides chosen for conflict-free mma fragment loads:
//   A1 stride 76 floats  -> bank (12*row + k) % 32 distinct over a warp
//   h  stride 132 floats -> bank (4*row + k) % 32 distinct
//   B  stride 136 floats -> bank (8*kmod + n) % 32 distinct
#define A1_STRIDE 76
#define H_STRIDE  132
#define B_STRIDE  136
#define TAB_STRIDE 132

#define OFF_LABEL 0                         // 128 * int
#define OFF_B1    512                       // 72*136 floats  = 39168 B
#define OFF_B2    (OFF_B1 + K1DIM*B_STRIDE*4)     // 128*136 floats = 69632 B
#define OFF_TAB   (OFF_B2 + EDIM*B_STRIDE*4)      // 64*132 floats  = 33792 B
#define OFF_BIAS1 (OFF_TAB + DDISP*TAB_STRIDE*4)  // 512 B
#define OFF_BIAS2 (OFF_BIAS1 + 512)
#define OFF_AH    (OFF_BIAS2 + 512)               // union: A1 (38912B) / h (67584B)
#define SMEM_TOTAL (OFF_AH + TILE_M*H_STRIDE*4)   // ~211.7 KB

// precomputed by prologue kernels
__device__ float g_W2p[EDIM*EDIM];    // [k][n] = sum_j W2[k][j]*Wp[j][n]
__device__ float g_bias2p[EDIM];      // b2 @ Wp_top
__device__ float g_table[DDISP*EDIM]; // fourier(d) @ Wp_bot

// ---------------- helpers ----------------
__device__ __forceinline__ uint32_t f2tf32(float x) {
    uint32_t r; asm("cvt.rna.tf32.f32 %0, %1;" : "=r"(r) : "f"(x)); return r;
}

__device__ __forceinline__ void mma_tf32(float c[4], const uint32_t a[4],
                                         uint32_t b0, uint32_t b1) {
    asm volatile(
        "mma.sync.aligned.m16n8k8.row.col.f32.tf32.tf32.f32 "
        "{%0,%1,%2,%3}, {%4,%5,%6,%7}, {%8,%9}, {%0,%1,%2,%3};"
        : "+f"(c[0]), "+f"(c[1]), "+f"(c[2]), "+f"(c[3])
        : "r"(a[0]), "r"(a[1]), "r"(a[2]), "r"(a[3]), "r"(b0), "r"(b1));
}

__device__ __forceinline__ float gelu_exact(float x) {
    return 0.5f * x * (1.0f + erff(x * 0.70710678118654752f));
}

// ---------------- prologue kernels ----------------
// g_W2p[k][n] = sum_j W2[k][j] * Wp[j][n];  g_bias2p[n] = sum_j b2[j]*Wp[j][n]
__global__ void prep_w2p_kernel(const float* __restrict__ W2, const float* __restrict__ b2,
                                const float* __restrict__ Wp) {
    __shared__ float w2row[EDIM];
    int k = blockIdx.x, e = threadIdx.x;
    w2row[e] = W2[k * EDIM + e];
    __syncthreads();
    float acc = 0.f;
    #pragma unroll 8
    for (int j = 0; j < EDIM; j++) acc += w2row[j] * Wp[j * EDIM + e];
    g_W2p[k * EDIM + e] = acc;
    if (k == 0) {
        float ba = 0.f;
        for (int j = 0; j < EDIM; j++) ba += b2[j] * Wp[j * EDIM + e];
        g_bias2p[e] = ba;
    }
}

// g_table[d][n] = sum_c fourier(d)[c] * Wp[(128+c)][n]
// sin/cos in double so --use_fast_math cannot degrade large-argument reduction.
__global__ void prep_table_kernel(const float* __restrict__ Wp) {
    __shared__ float f[31];
    int d = blockIdx.x, e = threadIdx.x;
    if (e == 0) {
        float coordf = (float)d * (float)(3.14 / 64.0);
        #pragma unroll
        for (int i = 0; i < 15; i++) {
            float fr = coordf * (float)(1 << i);   // f32 product, like the reference
            f[i] = (float)sin((double)fr);
            f[15 + i] = (float)cos((double)fr);
        }
        f[30] = coordf;
    }
    __syncthreads();
    float acc = 0.f;
    #pragma unroll
    for (int c = 0; c < 31; c++) acc += f[c] * Wp[(EDIM + c) * EDIM + e];
    g_table[d * EDIM + e] = acc;
}

// ---------------- main fused kernel ----------------
__global__ void __launch_bounds__(NTHR, 1)
propagation_kernel(const float* __restrict__ cost, const int* __restrict__ label,
                   const float* __restrict__ W1, const float* __restrict__ b1,
                   float* __restrict__ out_embed, float* __restrict__ out_label) {
    extern __shared__ char smem[];
    const int tid = threadIdx.x;
    const int wid = tid >> 5, lid = tid & 31;
    const int g = lid >> 2, ti = lid & 3;     // mma fragment coords
    const int wm = wid & 3, wn = wid >> 2;    // 4 m-slots x 2 n-slots
    const int mbase = wm * 32;                // warp m32
    const int nbase = wn * 64;                // warp n64

    int*      labels_s = (int*)(smem + OFF_LABEL);
    uint32_t* B1u  = (uint32_t*)(smem + OFF_B1);
    uint32_t* B2u  = (uint32_t*)(smem + OFF_B2);
    float*    tabs = (float*)(smem + OFF_TAB);
    float*    b1s  = (float*)(smem + OFF_BIAS1);
    float*    b2ps = (float*)(smem + OFF_BIAS2);
    uint32_t* AHu  = (uint32_t*)(smem + OFF_AH);

    // ---- load weights into SMEM once (persistent CTA) ----
    for (int idx = tid; idx < K1DIM * EDIM; idx += NTHR) {
        int k = idx >> 7, e = idx & 127;
        B1u[k * B_STRIDE + e] = f2tf32(W1[idx]);
    }
    for (int idx = tid; idx < EDIM * EDIM; idx += NTHR) {
        int k = idx >> 7, e = idx & 127;
        B2u[k * B_STRIDE + e] = f2tf32(g_W2p[idx]);
    }
    for (int t = tid; t < DDISP * EDIM; t += NTHR) {
        int d = t >> 7, e = t & 127;
        tabs[d * TAB_STRIDE + e] = g_table[t];
    }
    if (tid < EDIM) {
        b1s[tid] = b1[tid];
        b2ps[tid] = g_bias2p[tid];
    }
    __syncthreads();

    for (int tile = blockIdx.x; tile < NTILES; tile += GRID_X) {
        const int m0 = tile * TILE_M;

        // ---- labels ----
        if (tid < TILE_M) labels_s[tid] = label[m0 + tid];
        __syncthreads();

        // ---- gather: A1[row][k=g*9+c] = cost[pixel][grp][clip(d-4+c)] as tf32 ----
        for (int t = tid; t < TILE_M * GGRP; t += NTHR) {
            int row = t >> 3, grp = t & 7;
            int d = labels_s[row];
            const float* src = cost + (size_t)((m0 + row) >> 2) * (GGRP * DDISP) + grp * DDISP;
            uint32_t* dst = AHu + row * A1_STRIDE + grp * 9;
            #pragma unroll
            for (int c = 0; c < 9; c++) {
                int ix = d - 4 + c;
                ix = ix < 0 ? 0 : (ix > DDISP - 1 ? DDISP - 1 : ix);
                dst[c] = f2tf32(__ldg(src + ix));
            }
        }
        __syncthreads();

        // ---- GEMM1: h_pre = A1 @ W1  (K=72, 9 ksteps) ----
        float acc[2][8][4];
        #pragma unroll
        for (int i = 0; i < 2; i++)
            #pragma unroll
            for (int j = 0; j < 8; j++)
                #pragma unroll
                for (int u = 0; u < 4; u++) acc[i][j][u] = 0.f;

        #pragma unroll
        for (int s = 0; s < 9; s++) {
            int k0 = 8 * s + ti;
            uint32_t a[2][4];
            #pragma unroll
            for (int i = 0; i < 2; i++) {
                const uint32_t* ap = AHu + (mbase + 16 * i + g) * A1_STRIDE;
                a[i][0] = ap[k0];
                a[i][1] = ap[8 * A1_STRIDE + k0];
                a[i][2] = ap[k0 + 4];
                a[i][3] = ap[8 * A1_STRIDE + k0 + 4];
            }
            const uint32_t* bp0 = B1u + k0 * B_STRIDE + nbase + g;
            const uint32_t* bp1 = B1u + (k0 + 4) * B_STRIDE + nbase + g;
            #pragma unroll
            for (int j = 0; j < 8; j++) {
                uint32_t b0 = bp0[8 * j], b1v = bp1[8 * j];
                mma_tf32(acc[0][j], a[0], b0, b1v);
                mma_tf32(acc[1][j], a[1], b0, b1v);
            }
        }

        // ---- epilogue 1: gelu(x + b1) in regs ----
        #pragma unroll
        for (int i = 0; i < 2; i++)
            #pragma unroll
            for (int j = 0; j < 8; j++) {
                int c = nbase + 8 * j + 2 * ti;
                acc[i][j][0] = gelu_exact(acc[i][j][0] + b1s[c]);
                acc[i][j][1] = gelu_exact(acc[i][j][1] + b1s[c + 1]);
                acc[i][j][2] = gelu_exact(acc[i][j][2] + b1s[c]);
                acc[i][j][3] = gelu_exact(acc[i][j][3] + b1s[c + 1]);
            }

        __syncthreads();   // all warps done reading A1 before h overwrites the union

        // ---- store h (tf32) into union buffer, stride 132 ----
        #pragma unroll
        for (int i = 0; i < 2; i++) {
            int r = mbase + 16 * i + g;
            #pragma unroll
            for (int j = 0; j < 8; j++) {
                int c = nbase + 8 * j + 2 * ti;
                uint32_t* h0 = AHu + r * H_STRIDE + c;
                h0[0] = f2tf32(acc[i][j][0]);
                h0[1] = f2tf32(acc[i][j][1]);
                uint32_t* h1 = AHu + (r + 8) * H_STRIDE + c;
                h1[0] = f2tf32(acc[i][j][2]);
                h1[1] = f2tf32(acc[i][j][3]);
            }
        }
        __syncthreads();

        // ---- GEMM2: out_pre = h @ (W2@Wp)  (K=128, 16 ksteps) ----
        float acc2[2][8][4];
        #pragma unroll
        for (int i = 0; i < 2; i++)
            #pragma unroll
            for (int j = 0; j < 8; j++)
                #pragma unroll
                for (int u = 0; u < 4; u++) acc2[i][j][u] = 0.f;

        #pragma unroll
        for (int s = 0; s < 16; s++) {
            int k0 = 8 * s + ti;
            uint32_t a[2][4];
            #pragma unroll
            for (int i = 0; i < 2; i++) {
                const uint32_t* ap = AHu + (mbase + 16 * i + g) * H_STRIDE;
                a[i][0] = ap[k0];
                a[i][1] = ap[8 * H_STRIDE + k0];
                a[i][2] = ap[k0 + 4];
                a[i][3] = ap[8 * H_STRIDE + k0 + 4];
            }
            const uint32_t* bp0 = B2u + k0 * B_STRIDE + nbase + g;
            const uint32_t* bp1 = B2u + (k0 + 4) * B_STRIDE + nbase + g;
            #pragma unroll
            for (int j = 0; j < 8; j++) {
                uint32_t b0 = bp0[8 * j], b1v = bp1[8 * j];
                mma_tf32(acc2[0][j], a[0], b0, b1v);
                mma_tf32(acc2[1][j], a[1], b0, b1v);
            }
        }

        // ---- epilogue 2: out = pre + bias2p + table[d] ----
        #pragma unroll
        for (int i = 0; i < 2; i++) {
            int r0 = mbase + 16 * i + g;
            int r1 = r0 + 8;
            int d0 = labels_s[r0]; d0 = d0 < 0 ? 0 : (d0 > 63 ? 63 : d0);
            int d1 = labels_s[r1]; d1 = d1 < 0 ? 0 : (d1 > 63 ? 63 : d1);
            const float* t0 = tabs + d0 * TAB_STRIDE;
            const float* t1 = tabs + d1 * TAB_STRIDE;
            float* o0 = out_embed + (size_t)(m0 + r0) * EDIM;
            float* o1 = out_embed + (size_t)(m0 + r1) * EDIM;
            #pragma unroll
            for (int j = 0; j < 8; j++) {
                int c = nbase + 8 * j + 2 * ti;
                float2 bb = *(const float2*)(b2ps + c);
                float2 v0, v1;
                v0.x = acc2[i][j][0] + bb.x + t0[c];
                v0.y = acc2[i][j][1] + bb.y + t0[c + 1];
                v1.x = acc2[i][j][2] + bb.x + t1[c];
                v1.y = acc2[i][j][3] + bb.y + t1[c + 1];
                *(float2*)(o0 + c) = v0;
                *(float2*)(o1 + c) = v1;
            }
        }

        if (out_label != nullptr && tid < TILE_M)
            out_label[m0 + tid] = (float)labels_s[tid];

        __syncthreads();   // protect labels_s / AH before next tile
    }
}

// ---------------- launch ----------------
extern "C" void kernel_launch(void* const* d_in, const int* in_sizes, int n_in,
                              void* d_out, int out_size) {
    const float* cost  = (const float*)d_in[0];
    const int*   label = (const int*)d_in[1];
    // d_in[2] = context (unused: layers=[] passthrough)
    const float* W1 = (const float*)d_in[3];
    const float* b1 = (const float*)d_in[4];
    const float* W2 = (const float*)d_in[5];
    const float* b2 = (const float*)d_in[6];
    const float* Wp = (const float*)d_in[7];

    float* out = (float*)d_out;
    float* out_label = (out_size >= TOT_ELEMS) ? (out + EMB_ELEMS) : nullptr;

    cudaFuncSetAttribute(propagation_kernel,
                         cudaFuncAttributeMaxDynamicSharedMemorySize, SMEM_TOTAL);

    prep_w2p_kernel<<<128, 128>>>(W2, b2, Wp);
    prep_table_kernel<<<64, 128>>>(Wp);
    propagation_kernel<<<GRID_X, NTHR, SMEM_TOTAL>>>(cost, label, W1, b1, out, out_label);
}

// round 3
// speedup vs baseline: 1.0597x; 1.0597x over previous
#include <cuda_runtime.h>
#include <cuda_fp16.h>
#include <cstdint>

// ---------------- problem constants ----------------
#define GGRP   8
#define DDISP  64
#define EDIM   128
#define K1DIM  72            // G*9
#define K1PAD  80            // padded to 5 x k16 steps
#define MTOT   409600        // N*NS
#define TILE_M 128
#define NTILES 3200          // MTOT / TILE_M
#define GRID_X 152
#define NTHR   256           // 8 warps
#define EMB_ELEMS 52428800   // MTOT*EDIM
#define TOT_ELEMS 52838400   // + MTOT

// ---------------- smem layout ----------------
// f16 data stored as u32 words (pairs of halves, low half = even k).
// Conflict-free strides (in u32 units):
//   A1 stride 44 -> bank (12*row + kp) % 32 distinct over a warp
//   H  stride 68 -> bank ( 4*row + kp) % 32 distinct
//   B  stride 136-> bank ( 8*kp  + n ) % 32 distinct
#define A1_STRIDE 44         // 40 kp (K=80) + pad
#define H_STRIDE  68         // 64 kp (K=128) + pad
#define B_STRIDE  136        // 128 n + pad
#define TAB_STRIDE 132

#define OFF_LABEL 0                               // 128 ints
#define OFF_BIAS1 512
#define OFF_BIAS2 1024
#define OFF_B1    1536                            // 40*136*4  = 21760 B
#define OFF_B2    (OFF_B1 + 40*B_STRIDE*4)        // 64*136*4  = 34816 B
#define OFF_A1    (OFF_B2 + 64*B_STRIDE*4)        // 128*44*4  = 22528 B
#define OFF_H     (OFF_A1 + TILE_M*A1_STRIDE*4)   // 128*68*4  = 34816 B
#define OFF_TAB   (OFF_H + TILE_M*H_STRIDE*4)     // 64*132*4  = 33792 B
#define SMEM_TOTAL (OFF_TAB + DDISP*TAB_STRIDE*4) // 149248 B

// precomputed by prologue kernels
__device__ float g_W2p[EDIM*EDIM];    // [k][n] = sum_j W2[k][j]*Wp[j][n]
__device__ float g_bias2p[EDIM];      // b2 @ Wp_top
__device__ float g_table[DDISP*EDIM]; // fourier(d) @ Wp_bot

// ---------------- helpers ----------------
__device__ __forceinline__ void mma_f16(float c[4], const uint32_t a[4],
                                        uint32_t b0, uint32_t b1) {
    asm volatile(
        "mma.sync.aligned.m16n8k16.row.col.f32.f16.f16.f32 "
        "{%0,%1,%2,%3}, {%4,%5,%6,%7}, {%8,%9}, {%0,%1,%2,%3};"
        : "+f"(c[0]), "+f"(c[1]), "+f"(c[2]), "+f"(c[3])
        : "r"(a[0]), "r"(a[1]), "r"(a[2]), "r"(a[3]), "r"(b0), "r"(b1));
}

__device__ __forceinline__ float gelu_exact(float x) {
    return 0.5f * x * (1.0f + erff(x * 0.70710678118654752f));
}

__device__ __forceinline__ uint32_t pack_h2(float lo, float hi) {
    __half2 h = __floats2half2_rn(lo, hi);   // .x = lo (low half)
    return *(uint32_t*)&h;
}

// ---------------- prologue kernels ----------------
// g_W2p[k][n] = sum_j W2[k][j] * Wp[j][n], Wp_top cached in smem.
__global__ void prep_w2p_kernel(const float* __restrict__ W2, const float* __restrict__ b2,
                                const float* __restrict__ Wp) {
    extern __shared__ float Wps[];   // [128][128] = 64KB
    int tid = threadIdx.x;           // 128 threads
    for (int idx = tid; idx < EDIM * EDIM; idx += 128) Wps[idx] = Wp[idx];
    __syncthreads();
    #pragma unroll
    for (int kr = 0; kr < 8; kr++) {
        int k = blockIdx.x * 8 + kr;
        float acc = 0.f;
        #pragma unroll 8
        for (int j = 0; j < EDIM; j++) acc += W2[k * EDIM + j] * Wps[j * EDIM + tid];
        g_W2p[k * EDIM + tid] = acc;
    }
    if (blockIdx.x == 0) {
        float ba = 0.f;
        for (int j = 0; j < EDIM; j++) ba += b2[j] * Wps[j * EDIM + tid];
        g_bias2p[tid] = ba;
    }
}

// g_table[d][n] = sum_c fourier(d)[c] * Wp[(128+c)][n]
__global__ void prep_table_kernel(const float* __restrict__ Wp) {
    __shared__ float f[31];
    int d = blockIdx.x, e = threadIdx.x;
    if (e == 0) {
        float coordf = (float)d * (float)(3.14 / 64.0);
        #pragma unroll
        for (int i = 0; i < 15; i++) {
            float fr = coordf * (float)(1 << i);
            f[i] = (float)sin((double)fr);
            f[15 + i] = (float)cos((double)fr);
        }
        f[30] = coordf;
    }
    __syncthreads();
    float acc = 0.f;
    #pragma unroll
    for (int c = 0; c < 31; c++) acc += f[c] * Wp[(EDIM + c) * EDIM + e];
    g_table[d * EDIM + e] = acc;
}

// ---------------- main fused kernel ----------------
__global__ void __launch_bounds__(NTHR, 1)
propagation_kernel(const float* __restrict__ cost, const int* __restrict__ label,
                   const float* __restrict__ W1, const float* __restrict__ b1,
                   float* __restrict__ out_embed, float* __restrict__ out_label) {
    extern __shared__ char smem[];
    const int tid = threadIdx.x;
    const int wid = tid >> 5, lid = tid & 31;
    const int g = lid >> 2, ti = lid & 3;     // mma fragment coords
    const int wm = wid & 3, wn = wid >> 2;    // 4 m-slots x 2 n-slots
    const int mbase = wm * 32;                // warp m32
    const int nbase = wn * 64;                // warp n64

    int*      labels_s = (int*)(smem + OFF_LABEL);
    float*    b1s  = (float*)(smem + OFF_BIAS1);
    float*    b2ps = (float*)(smem + OFF_BIAS2);
    uint32_t* B1u  = (uint32_t*)(smem + OFF_B1);
    uint32_t* B2u  = (uint32_t*)(smem + OFF_B2);
    uint32_t* A1u  = (uint32_t*)(smem + OFF_A1);
    __half*   A1h  = (__half*)(smem + OFF_A1);
    uint32_t* Hu   = (uint32_t*)(smem + OFF_H);
    float*    tabs = (float*)(smem + OFF_TAB);

    // ---- init weights in SMEM once (persistent CTA) ----
    // zero B1 (covers K pad 72..79) and A1 pad words (kp 36..39)
    for (int i = tid; i < 40 * B_STRIDE; i += NTHR) B1u[i] = 0;
    for (int i = tid; i < TILE_M * 4; i += NTHR)
        A1u[(i >> 2) * A1_STRIDE + 36 + (i & 3)] = 0;
    __syncthreads();
    // B1[(k/2)][n], half slot k&1  <- W1[k][n]
    {
        __half* B1h = (__half*)B1u;
        for (int idx = tid; idx < K1DIM * EDIM; idx += NTHR) {
            int k = idx >> 7, n = idx & 127;
            B1h[((k >> 1) * B_STRIDE + n) * 2 + (k & 1)] = __float2half(W1[idx]);
        }
        __half* B2h = (__half*)B2u;
        for (int idx = tid; idx < EDIM * EDIM; idx += NTHR) {
            int k = idx >> 7, n = idx & 127;
            B2h[((k >> 1) * B_STRIDE + n) * 2 + (k & 1)] = __float2half(g_W2p[idx]);
        }
    }
    for (int t = tid; t < DDISP * EDIM; t += NTHR) {
        int d = t >> 7, e = t & 127;
        tabs[d * TAB_STRIDE + e] = g_table[t];
    }
    if (tid < EDIM) {
        b1s[tid] = b1[tid];
        b2ps[tid] = g_bias2p[tid];
    }
    __syncthreads();

    for (int tile = blockIdx.x; tile < NTILES; tile += GRID_X) {
        const int m0 = tile * TILE_M;

        // ---- labels ----
        if (tid < TILE_M) labels_s[tid] = label[m0 + tid];
        __syncthreads();

        // ---- gather: A1[row][k=9g+c] = f16(cost[pix][grp][clip(d-4+c)]) ----
        for (int t = tid; t < TILE_M * GGRP; t += NTHR) {
            int row = t >> 3, grp = t & 7;
            int d = labels_s[row];
            const float* src = cost + (size_t)((m0 + row) >> 2) * (GGRP * DDISP) + grp * DDISP;
            __half* dst = A1h + row * (A1_STRIDE * 2) + grp * 9;
            #pragma unroll
            for (int c = 0; c < 9; c++) {
                int ix = d - 4 + c;
                ix = ix < 0 ? 0 : (ix > DDISP - 1 ? DDISP - 1 : ix);
                dst[c] = __float2half(__ldg(src + ix));
            }
        }
        __syncthreads();

        // ---- GEMM1: h_pre = A1 @ W1  (K=80, 5 k16 steps) ----
        float acc[2][8][4];
        #pragma unroll
        for (int i = 0; i < 2; i++)
            #pragma unroll
            for (int j = 0; j < 8; j++)
                #pragma unroll
                for (int u = 0; u < 4; u++) acc[i][j][u] = 0.f;

        #pragma unroll
        for (int s = 0; s < 5; s++) {
            int kp0 = 8 * s + ti;
            uint32_t a[2][4];
            #pragma unroll
            for (int i = 0; i < 2; i++) {
                const uint32_t* ap = A1u + (mbase + 16 * i + g) * A1_STRIDE;
                a[i][0] = ap[kp0];
                a[i][1] = ap[8 * A1_STRIDE + kp0];
                a[i][2] = ap[kp0 + 4];
                a[i][3] = ap[8 * A1_STRIDE + kp0 + 4];
            }
            const uint32_t* bp0 = B1u + kp0 * B_STRIDE + nbase + g;
            const uint32_t* bp1 = B1u + (kp0 + 4) * B_STRIDE + nbase + g;
            #pragma unroll
            for (int j = 0; j < 8; j++) {
                uint32_t b0 = bp0[8 * j], b1v = bp1[8 * j];
                mma_f16(acc[0][j], a[0], b0, b1v);
                mma_f16(acc[1][j], a[1], b0, b1v);
            }
        }

        // ---- epilogue 1: gelu(x + b1), pack to f16 ----
        __syncthreads();   // all warps done reading A1 (H is separate, but keep order tight)
        #pragma unroll
        for (int i = 0; i < 2; i++) {
            int r = mbase + 16 * i + g;
            #pragma unroll
            for (int j = 0; j < 8; j++) {
                int c = nbase + 8 * j + 2 * ti;
                float g0 = gelu_exact(acc[i][j][0] + b1s[c]);
                float g1 = gelu_exact(acc[i][j][1] + b1s[c + 1]);
                float g2 = gelu_exact(acc[i][j][2] + b1s[c]);
                float g3 = gelu_exact(acc[i][j][3] + b1s[c + 1]);
                Hu[r * H_STRIDE + (c >> 1)] = pack_h2(g0, g1);
                Hu[(r + 8) * H_STRIDE + (c >> 1)] = pack_h2(g2, g3);
            }
        }
        __syncthreads();

        // ---- GEMM2: out_pre = h @ (W2@Wp)  (K=128, 8 k16 steps) ----
        float acc2[2][8][4];
        #pragma unroll
        for (int i = 0; i < 2; i++)
            #pragma unroll
            for (int j = 0; j < 8; j++)
                #pragma unroll
                for (int u = 0; u < 4; u++) acc2[i][j][u] = 0.f;

        #pragma unroll
        for (int s = 0; s < 8; s++) {
            int kp0 = 8 * s + ti;
            uint32_t a[2][4];
            #pragma unroll
            for (int i = 0; i < 2; i++) {
                const uint32_t* ap = Hu + (mbase + 16 * i + g) * H_STRIDE;
                a[i][0] = ap[kp0];
                a[i][1] = ap[8 * H_STRIDE + kp0];
                a[i][2] = ap[kp0 + 4];
                a[i][3] = ap[8 * H_STRIDE + kp0 + 4];
            }
            const uint32_t* bp0 = B2u + kp0 * B_STRIDE + nbase + g;
            const uint32_t* bp1 = B2u + (kp0 + 4) * B_STRIDE + nbase + g;
            #pragma unroll
            for (int j = 0; j < 8; j++) {
                uint32_t b0 = bp0[8 * j], b1v = bp1[8 * j];
                mma_f16(acc2[0][j], a[0], b0, b1v);
                mma_f16(acc2[1][j], a[1], b0, b1v);
            }
        }

        // ---- epilogue 2: out = pre + bias2p + table[d] ----
        #pragma unroll
        for (int i = 0; i < 2; i++) {
            int r0 = mbase + 16 * i + g;
            int r1 = r0 + 8;
            int d0 = labels_s[r0]; d0 = d0 < 0 ? 0 : (d0 > 63 ? 63 : d0);
            int d1 = labels_s[r1]; d1 = d1 < 0 ? 0 : (d1 > 63 ? 63 : d1);
            const float* t0 = tabs + d0 * TAB_STRIDE;
            const float* t1 = tabs + d1 * TAB_STRIDE;
            float* o0 = out_embed + (size_t)(m0 + r0) * EDIM;
            float* o1 = out_embed + (size_t)(m0 + r1) * EDIM;
            #pragma unroll
            for (int j = 0; j < 8; j++) {
                int c = nbase + 8 * j + 2 * ti;
                float2 bb = *(const float2*)(b2ps + c);
                float2 v0, v1;
                v0.x = acc2[i][j][0] + bb.x + t0[c];
                v0.y = acc2[i][j][1] + bb.y + t0[c + 1];
                v1.x = acc2[i][j][2] + bb.x + t1[c];
                v1.y = acc2[i][j][3] + bb.y + t1[c + 1];
                *(float2*)(o0 + c) = v0;
                *(float2*)(o1 + c) = v1;
            }
        }

        if (out_label != nullptr && tid < TILE_M)
            out_label[m0 + tid] = (float)labels_s[tid];

        __syncthreads();   // protect labels_s / A1 before next tile
    }
}

// ---------------- launch ----------------
extern "C" void kernel_launch(void* const* d_in, const int* in_sizes, int n_in,
                              void* d_out, int out_size) {
    const float* cost  = (const float*)d_in[0];
    const int*   label = (const int*)d_in[1];
    // d_in[2] = context (unused: layers=[] passthrough)
    const float* W1 = (const float*)d_in[3];
    const float* b1 = (const float*)d_in[4];
    const float* W2 = (const float*)d_in[5];
    const float* b2 = (const float*)d_in[6];
    const float* Wp = (const float*)d_in[7];

    float* out = (float*)d_out;
    float* out_label = (out_size >= TOT_ELEMS) ? (out + EMB_ELEMS) : nullptr;

    cudaFuncSetAttribute(prep_w2p_kernel,
                         cudaFuncAttributeMaxDynamicSharedMemorySize, 65536);
    cudaFuncSetAttribute(propagation_kernel,
                         cudaFuncAttributeMaxDynamicSharedMemorySize, SMEM_TOTAL);

    prep_w2p_kernel<<<16, 128, 65536>>>(W2, b2, Wp);
    prep_table_kernel<<<64, 128>>>(Wp);
    propagation_kernel<<<GRID_X, NTHR, SMEM_TOTAL>>>(cost, label, W1, b1, out, out_label);
}

// round 4
// speedup vs baseline: 1.9123x; 1.8046x over previous
#include <cuda_runtime.h>
#include <cuda_fp16.h>
#include <cstdint>

// ---------------- problem constants ----------------
#define GGRP   8
#define DDISP  64
#define EDIM   128
#define K1DIM  72            // G*9
#define MTOT   409600        // N*NS
#define TILE_M 128
#define NTILES 3200          // MTOT / TILE_M
#define GRID_X 152
#define NTHR   256           // 8 warps, each owns m16 x n128
#define EMB_ELEMS 52428800   // MTOT*EDIM
#define TOT_ELEMS 52838400   // + MTOT

// ---------------- smem layout ----------------
// u32-unit strides, conflict-free:
//   A1 stride 44 -> bank (12*row + kp) % 32 distinct over warp
//   B  stride 136-> bank ( 8*kp  + n ) % 32 distinct
#define A1_STRIDE 44
#define B_STRIDE  136
#define TAB_STRIDE 132

#define OFF_LABEL 0                               // 2 x 128 ints (double buffer)
#define OFF_BIAS1 1024                            // 128 f
#define OFF_B1    1536                            // 40*136*4 = 21760
#define OFF_B2    (OFF_B1 + 40*B_STRIDE*4)        // 64*136*4 = 34816
#define OFF_A1    (OFF_B2 + 64*B_STRIDE*4)        // 128*44*4 = 22528
#define OFF_TAB   (OFF_A1 + TILE_M*A1_STRIDE*4)   // 64*132*4 = 33792
#define SMEM_TOTAL (OFF_TAB + DDISP*TAB_STRIDE*4) // 114432 B

// precomputed by prologue kernels
__device__ float g_W2p[EDIM*EDIM];    // [k][n] = sum_j W2[k][j]*Wp[j][n]
__device__ float g_bias2p[EDIM];      // b2 @ Wp_top
__device__ float g_table[DDISP*EDIM]; // fourier(d) @ Wp_bot + bias2p

// ---------------- helpers ----------------
__device__ __forceinline__ void mma_f16(float c[4], uint32_t a0, uint32_t a1,
                                        uint32_t a2, uint32_t a3,
                                        uint32_t b0, uint32_t b1) {
    asm volatile(
        "mma.sync.aligned.m16n8k16.row.col.f32.f16.f16.f32 "
        "{%0,%1,%2,%3}, {%4,%5,%6,%7}, {%8,%9}, {%0,%1,%2,%3};"
        : "+f"(c[0]), "+f"(c[1]), "+f"(c[2]), "+f"(c[3])
        : "r"(a0), "r"(a1), "r"(a2), "r"(a3), "r"(b0), "r"(b1));
}

// branchless tanh-form gelu: x*sigmoid(1.5957691x + 0.0713548x^3)
__device__ __forceinline__ float gelu_fast(float x) {
    float p = x * fmaf(x * x, 0.0713548163f, 1.5957691216f);   // 2z
    float e;
    asm("ex2.approx.ftz.f32 %0, %1;" : "=f"(e) : "f"(-1.4426950408889634f * p));
    float r;
    asm("rcp.approx.ftz.f32 %0, %1;" : "=f"(r) : "f"(1.0f + e));
    return x * r;
}

__device__ __forceinline__ uint32_t pack_h2(float lo, float hi) {
    __half2 h = __floats2half2_rn(lo, hi);
    return *(uint32_t*)&h;
}

// ---------------- prologue kernels ----------------
// g_W2p[k][n] = sum_j W2[k][j]*Wp[j][n]; split-j over 2 thread groups.
__global__ void prep_w2p_kernel(const float* __restrict__ W2, const float* __restrict__ b2,
                                const float* __restrict__ Wp) {
    __shared__ float red[256];
    int k = blockIdx.x;
    int n = threadIdx.x & 127, jh = threadIdx.x >> 7;
    const float* w2r = W2 + k * EDIM + jh * 64;
    const float* wp  = Wp + (size_t)(jh * 64) * EDIM + n;
    float acc = 0.f;
    #pragma unroll 16
    for (int j = 0; j < 64; j++) acc += __ldg(w2r + j) * __ldg(wp + (size_t)j * EDIM);
    red[threadIdx.x] = acc;
    __syncthreads();
    if (jh == 0) {
        g_W2p[k * EDIM + n] = red[n] + red[128 + n];
        if (k == 0) {
            float ba = 0.f;
            #pragma unroll 8
            for (int j = 0; j < EDIM; j++) ba += b2[j] * Wp[(size_t)j * EDIM + n];
            g_bias2p[n] = ba;
        }
    }
}

// g_table[d][n] = fourier(d) @ Wp_bot + bias2p  (runs after prep_w2p in-stream)
__global__ void prep_table_kernel(const float* __restrict__ Wp) {
    __shared__ float f[31];
    int d = blockIdx.x, e = threadIdx.x;
    if (e < 15) {
        float coordf = (float)d * (float)(3.14 / 64.0);
        float fr = coordf * (float)(1 << e);
        f[e] = (float)sin((double)fr);
        f[15 + e] = (float)cos((double)fr);
        if (e == 0) f[30] = coordf;
    }
    __syncthreads();
    float acc = g_bias2p[e];
    #pragma unroll
    for (int c = 0; c < 31; c++) acc += f[c] * Wp[(EDIM + c) * EDIM + e];
    g_table[d * EDIM + e] = acc;
}

// ---------------- main fused kernel ----------------
__global__ void __launch_bounds__(NTHR, 1)
propagation_kernel(const float* __restrict__ cost, const int* __restrict__ label,
                   const float* __restrict__ W1, const float* __restrict__ b1,
                   float* __restrict__ out_embed, float* __restrict__ out_label) {
    extern __shared__ char smem[];
    const int tid = threadIdx.x;
    const int wid = tid >> 5, lid = tid & 31;
    const int g = lid >> 2, ti = lid & 3;     // mma fragment coords
    const int mbase = wid * 16;               // warp owns rows [mbase, mbase+16)
    const int grow = mbase + (lid >> 1);      // gather row for this thread
    const int grp4 = (lid & 1) * 4;           // gather group base (4 groups each)

    int*      labels_s = (int*)(smem + OFF_LABEL);
    float*    b1s  = (float*)(smem + OFF_BIAS1);
    uint32_t* B1u  = (uint32_t*)(smem + OFF_B1);
    uint32_t* B2u  = (uint32_t*)(smem + OFF_B2);
    uint32_t* A1u  = (uint32_t*)(smem + OFF_A1);
    float*    tabs = (float*)(smem + OFF_TAB);
    uint32_t* A1w  = A1u + mbase * A1_STRIDE;            // warp-private A1 slice
    uint32_t* Gdst = A1w + (lid >> 1) * A1_STRIDE + (lid & 1) * 18;  // this thread's 18 words

    // ---- weights into SMEM once (persistent CTA) ----
    for (int i = tid; i < 40 * B_STRIDE; i += NTHR) B1u[i] = 0;
    __syncthreads();
    {
        __half* B1h = (__half*)B1u;
        for (int idx = tid; idx < K1DIM * EDIM; idx += NTHR) {
            int k = idx >> 7, n = idx & 127;
            B1h[(k >> 1) * (B_STRIDE * 2) + n * 2 + (k & 1)] = __float2half(W1[idx]);
        }
        __half* B2h = (__half*)B2u;
        for (int idx = tid; idx < EDIM * EDIM; idx += NTHR) {
            int k = idx >> 7, n = idx & 127;
            B2h[(k >> 1) * (B_STRIDE * 2) + n * 2 + (k & 1)] = __float2half(g_W2p[idx]);
        }
    }
    for (int t = tid; t < DDISP * EDIM; t += NTHR)
        tabs[(t >> 7) * TAB_STRIDE + (t & 127)] = g_table[t];
    if (tid < EDIM) b1s[tid] = b1[tid];
    // zero A1 K-pad words (kp 36..39) for this warp's rows
    for (int i = lid; i < 64; i += 32)
        A1w[(i >> 2) * A1_STRIDE + 36 + (i & 3)] = 0;

    // ---- first tile gather (tile = blockIdx.x) ----
    {
        int m0p = blockIdx.x * TILE_M;
        int draw = __ldg(label + m0p + grow);
        int dcl = draw < 0 ? 0 : (draw > 63 ? 63 : draw);
        if ((lid & 1) == 0) {
            labels_s[grow] = draw;
            if (out_label) out_label[m0p + grow] = (float)draw;
        }
        const float* rec = cost + (size_t)((m0p + grow) >> 2) * (GGRP * DDISP);
        float gv[36];
        #pragma unroll
        for (int gi = 0; gi < 4; gi++) {
            const float* src = rec + (grp4 + gi) * DDISP;
            #pragma unroll
            for (int c = 0; c < 9; c++) {
                int ix = dcl - 4 + c;
                ix = ix < 0 ? 0 : (ix > 63 ? 63 : ix);
                gv[gi * 9 + c] = __ldg(src + ix);
            }
        }
        #pragma unroll
        for (int w = 0; w < 18; w++) Gdst[w] = pack_h2(gv[2 * w], gv[2 * w + 1]);
    }
    __syncthreads();

    int cb = 0;
    for (int tile = blockIdx.x; tile < NTILES; tile += GRID_X) {
        const int m0 = tile * TILE_M;
        const int nxt = tile + GRID_X;
        const bool hn = nxt < NTILES;

        // ---- prefetch next tile's label (latency hidden under GEMM1) ----
        int draw = 0;
        if (hn) draw = __ldg(label + nxt * TILE_M + grow);

        // ---- GEMM1: m16 x n128, K=80 (5 k16 steps) ----
        float acc1[16][4];
        #pragma unroll
        for (int j = 0; j < 16; j++)
            #pragma unroll
            for (int u = 0; u < 4; u++) acc1[j][u] = 0.f;

        #pragma unroll
        for (int s = 0; s < 5; s++) {
            int kp0 = 8 * s + ti;
            uint32_t a0 = A1w[g * A1_STRIDE + kp0];
            uint32_t a1 = A1w[(g + 8) * A1_STRIDE + kp0];
            uint32_t a2 = A1w[g * A1_STRIDE + kp0 + 4];
            uint32_t a3 = A1w[(g + 8) * A1_STRIDE + kp0 + 4];
            const uint32_t* bp = B1u + kp0 * B_STRIDE + g;
            const uint32_t* bq = B1u + (kp0 + 4) * B_STRIDE + g;
            #pragma unroll
            for (int j = 0; j < 16; j++)
                mma_f16(acc1[j], a0, a1, a2, a3, bp[8 * j], bq[8 * j]);
        }
        __syncwarp();   // all lanes done reading A1 before next-tile gather STS

        // ---- gelu(x+b1) and repack C-frags directly as GEMM2 A-frags ----
        uint32_t ha[8][4];
        #pragma unroll
        for (int s = 0; s < 8; s++) {
            int j0 = 2 * s, j1 = 2 * s + 1;
            float2 bb0 = *(const float2*)(b1s + 8 * j0 + 2 * ti);
            float2 bb1 = *(const float2*)(b1s + 8 * j1 + 2 * ti);
            ha[s][0] = pack_h2(gelu_fast(acc1[j0][0] + bb0.x), gelu_fast(acc1[j0][1] + bb0.y));
            ha[s][1] = pack_h2(gelu_fast(acc1[j0][2] + bb0.x), gelu_fast(acc1[j0][3] + bb0.y));
            ha[s][2] = pack_h2(gelu_fast(acc1[j1][0] + bb1.x), gelu_fast(acc1[j1][1] + bb1.y));
            ha[s][3] = pack_h2(gelu_fast(acc1[j1][2] + bb1.x), gelu_fast(acc1[j1][3] + bb1.y));
        }

        // ---- issue next-tile gather loads (consumed after GEMM2) ----
        float gv[36];
        if (hn) {
            int dcl = draw < 0 ? 0 : (draw > 63 ? 63 : draw);
            const float* rec = cost + (size_t)((nxt * TILE_M + grow) >> 2) * (GGRP * DDISP);
            #pragma unroll
            for (int gi = 0; gi < 4; gi++) {
                const float* src = rec + (grp4 + gi) * DDISP;
                #pragma unroll
                for (int c = 0; c < 9; c++) {
                    int ix = dcl - 4 + c;
                    ix = ix < 0 ? 0 : (ix > 63 ? 63 : ix);
                    gv[gi * 9 + c] = __ldg(src + ix);
                }
            }
        }

        // ---- GEMM2: A from registers, K=128 (8 k16 steps) ----
        float acc2[16][4];
        #pragma unroll
        for (int j = 0; j < 16; j++)
            #pragma unroll
            for (int u = 0; u < 4; u++) acc2[j][u] = 0.f;

        #pragma unroll
        for (int s = 0; s < 8; s++) {
            int kp0 = 8 * s + ti;
            const uint32_t* bp = B2u + kp0 * B_STRIDE + g;
            const uint32_t* bq = B2u + (kp0 + 4) * B_STRIDE + g;
            #pragma unroll
            for (int j = 0; j < 16; j++)
                mma_f16(acc2[j], ha[s][0], ha[s][1], ha[s][2], ha[s][3],
                        bp[8 * j], bq[8 * j]);
        }

        // ---- epilogue: out = acc2 + table[d] (bias2p folded into table) ----
        {
            int r0 = mbase + g, r1 = r0 + 8;
            int d0 = labels_s[cb * TILE_M + r0];
            int d1 = labels_s[cb * TILE_M + r1];
            d0 = d0 < 0 ? 0 : (d0 > 63 ? 63 : d0);
            d1 = d1 < 0 ? 0 : (d1 > 63 ? 63 : d1);
            const float* t0 = tabs + d0 * TAB_STRIDE + 2 * ti;
            const float* t1 = tabs + d1 * TAB_STRIDE + 2 * ti;
            float* o0 = out_embed + (size_t)(m0 + r0) * EDIM + 2 * ti;
            float* o1 = out_embed + (size_t)(m0 + r1) * EDIM + 2 * ti;
            #pragma unroll
            for (int j = 0; j < 16; j++) {
                float2 tv0 = *(const float2*)(t0 + 8 * j);
                float2 tv1 = *(const float2*)(t1 + 8 * j);
                float2 v0, v1;
                v0.x = acc2[j][0] + tv0.x;  v0.y = acc2[j][1] + tv0.y;
                v1.x = acc2[j][2] + tv1.x;  v1.y = acc2[j][3] + tv1.y;
                *(float2*)(o0 + 8 * j) = v0;
                *(float2*)(o1 + 8 * j) = v1;
            }
        }

        // ---- commit next-tile gather + labels (warp-private regions) ----
        if (hn) {
            #pragma unroll
            for (int w = 0; w < 18; w++) Gdst[w] = pack_h2(gv[2 * w], gv[2 * w + 1]);
            if ((lid & 1) == 0) {
                labels_s[(cb ^ 1) * TILE_M + grow] = draw;
                if (out_label) out_label[nxt * TILE_M + grow] = (float)draw;
            }
        }
        __syncwarp();   // STS visible before next iteration's LDS
        cb ^= 1;
    }
}

// ---------------- launch ----------------
extern "C" void kernel_launch(void* const* d_in, const int* in_sizes, int n_in,
                              void* d_out, int out_size) {
    const float* cost  = (const float*)d_in[0];
    const int*   label = (const int*)d_in[1];
    // d_in[2] = context (unused: layers=[] passthrough)
    const float* W1 = (const float*)d_in[3];
    const float* b1 = (const float*)d_in[4];
    const float* W2 = (const float*)d_in[5];
    const float* b2 = (const float*)d_in[6];
    const float* Wp = (const float*)d_in[7];

    float* out = (float*)d_out;
    float* out_label = (out_size >= TOT_ELEMS) ? (out + EMB_ELEMS) : nullptr;

    cudaFuncSetAttribute(propagation_kernel,
                         cudaFuncAttributeMaxDynamicSharedMemorySize, SMEM_TOTAL);

    prep_w2p_kernel<<<128, 256>>>(W2, b2, Wp);
    prep_table_kernel<<<64, 128>>>(Wp);
    propagation_kernel<<<GRID_X, NTHR, SMEM_TOTAL>>>(cost, label, W1, b1, out, out_label);
}

// round 5
// speedup vs baseline: 1.9245x; 1.0064x over previous
#include <cuda_runtime.h>
#include <cuda_fp16.h>
#include <cstdint>

// ---------------- problem constants ----------------
#define GGRP   8
#define DDISP  64
#define EDIM   128
#define K1DIM  72            // G*9
#define MTOT   409600        // N*NS
#define TILE_M 128
#define NTILES 3200          // MTOT / TILE_M
#define GRID_X 152
#define NTHR   256           // 8 warps, each owns m16 x n128
#define EMB_ELEMS 52428800   // MTOT*EDIM
#define TOT_ELEMS 52838400   // + MTOT

// ---------------- smem layout ----------------
// A1: u32 words, row stride 44 (bank 12r+kp distinct)   [double buffered]
// B1/B2: PAIR layout for LDS.64: pair(kp0=8s+ti, kp0+4) at
//        pair_index = s*528 + ti*132 + n   (bank phase 4ti+8j+g distinct)
#define A1_STRIDE 44
#define PAIR_TI   132
#define PAIR_S    528
#define TAB_STRIDE 132

#define OFF_LABEL 0                               // 2 x 128 ints
#define OFF_BIAS1 1024                            // 128 f
#define OFF_BIAS2 1536                            // 128 f
#define OFF_B1    2048                            // 5*528 pairs *8B  = 21120
#define OFF_B2    (OFF_B1 + 5*PAIR_S*8)           // 8*528 pairs *8B  = 33792
#define OFF_A1    (OFF_B2 + 8*PAIR_S*8)           // 2 * 128*44*4     = 45056
#define A1_BUF_BYTES (TILE_M*A1_STRIDE*4)
#define OFF_TAB   (OFF_A1 + 2*A1_BUF_BYTES)       // 64*132*4 = 33792
#define SMEM_TOTAL (OFF_TAB + DDISP*TAB_STRIDE*4) // 135808 B

// prologue staging (reused regions):
//   W2s  (f16, word[r][jp], stride 68) at OFF_A1   (34816 <= 45056)
//   WpTs (f16, word[n][jp], stride 66) at OFF_TAB  (33792 exact)
//   f-scratch (64 x 32 f32)            at OFF_A1 after fold
#define W2S_STRIDE 68
#define WPT_STRIDE 66

// ---------------- helpers ----------------
__device__ __forceinline__ void mma_f16(float c[4], uint32_t a0, uint32_t a1,
                                        uint32_t a2, uint32_t a3,
                                        uint32_t b0, uint32_t b1) {
    asm volatile(
        "mma.sync.aligned.m16n8k16.row.col.f32.f16.f16.f32 "
        "{%0,%1,%2,%3}, {%4,%5,%6,%7}, {%8,%9}, {%0,%1,%2,%3};"
        : "+f"(c[0]), "+f"(c[1]), "+f"(c[2]), "+f"(c[3])
        : "r"(a0), "r"(a1), "r"(a2), "r"(a3), "r"(b0), "r"(b1));
}

// branchless tanh-form gelu: x*sigmoid(1.5957691x + 0.0713548x^3)
__device__ __forceinline__ float gelu_fast(float x) {
    float p = x * fmaf(x * x, 0.0713548163f, 1.5957691216f);
    float e;
    asm("ex2.approx.ftz.f32 %0, %1;" : "=f"(e) : "f"(-1.4426950408889634f * p));
    float r;
    asm("rcp.approx.ftz.f32 %0, %1;" : "=f"(r) : "f"(1.0f + e));
    return x * r;
}

__device__ __forceinline__ uint32_t pack_h2(float lo, float hi) {
    __half2 h = __floats2half2_rn(lo, hi);
    return *(uint32_t*)&h;
}

// half index in B pair layout for element (k, n)
__device__ __forceinline__ int pair_half_idx(int k, int n) {
    int kp = k >> 1, h = k & 1;
    int s = kp >> 3, rem = kp & 7;
    int ti = rem & 3, w = rem >> 2;
    return ((s * PAIR_S + ti * PAIR_TI + n) * 2 + w) * 2 + h;
}

// ---------------- single fused kernel ----------------
__global__ void __launch_bounds__(NTHR, 1)
propagation_kernel(const float* __restrict__ cost, const int* __restrict__ label,
                   const float* __restrict__ W1, const float* __restrict__ b1,
                   const float* __restrict__ W2, const float* __restrict__ b2,
                   const float* __restrict__ Wp,
                   float* __restrict__ out_embed, float* __restrict__ out_label) {
    extern __shared__ char smem[];
    const int tid = threadIdx.x;
    const int wid = tid >> 5, lid = tid & 31;
    const int g = lid >> 2, ti = lid & 3;     // mma fragment coords
    const int mbase = wid * 16;               // warp owns rows [mbase, mbase+16)
    const int grow = mbase + (lid >> 1);      // gather row for this thread
    const int grp4 = (lid & 1) * 4;           // gather group base

    int*      labels_s = (int*)(smem + OFF_LABEL);
    float*    b1s   = (float*)(smem + OFF_BIAS1);
    float*    b2ps  = (float*)(smem + OFF_BIAS2);
    uint2*    B1p   = (uint2*)(smem + OFF_B1);
    uint2*    B2p   = (uint2*)(smem + OFF_B2);
    __half*   B1h   = (__half*)(smem + OFF_B1);
    __half*   B2h   = (__half*)(smem + OFF_B2);
    uint32_t* A1u   = (uint32_t*)(smem + OFF_A1);
    float*    tabs  = (float*)(smem + OFF_TAB);

    // ================= PROLOGUE =================
    // --- stage W2 (f16, [r][j] k-major) into A1 region; WpT (f16, [n][j]) into TAB region ---
    {
        __half* W2sh  = (__half*)(smem + OFF_A1);
        __half* WpTsh = (__half*)(smem + OFF_TAB);
        for (int idx = tid; idx < EDIM * EDIM; idx += NTHR) {
            int r = idx >> 7, j = idx & 127;
            W2sh[(r * W2S_STRIDE + (j >> 1)) * 2 + (j & 1)] = __float2half(__ldg(W2 + idx));
            // idx = j*128 + n for Wp (coalesced read), scattered f16 store
            int jj = idx >> 7, n = idx & 127;
            WpTsh[(n * WPT_STRIDE + (jj >> 1)) * 2 + (jj & 1)] = __float2half(__ldg(Wp + idx));
        }
        // W1 -> B1 pair layout
        for (int idx = tid; idx < K1DIM * EDIM; idx += NTHR) {
            int k = idx >> 7, n = idx & 127;
            B1h[pair_half_idx(k, n)] = __float2half(__ldg(W1 + idx));
        }
        // zero B1 pad words (kp 36..39): s=4, w=1
        for (int i = tid; i < 512; i += NTHR) {
            int t4 = i >> 7, n = i & 127;
            ((uint32_t*)B1p)[(4 * PAIR_S + t4 * PAIR_TI + n) * 2 + 1] = 0;
        }
        if (tid < EDIM) b1s[tid] = __ldg(b1 + tid);
    }
    __syncthreads();

    // --- fold W2p = W2 @ Wp_top with tensor cores; each warp: rows 16*wid..+15 ---
    {
        const uint32_t* W2s  = (const uint32_t*)(smem + OFF_A1);
        const uint32_t* WpTs = (const uint32_t*)(smem + OFF_TAB);
        float facc[16][4];
        #pragma unroll
        for (int j = 0; j < 16; j++)
            #pragma unroll
            for (int u = 0; u < 4; u++) facc[j][u] = 0.f;
        #pragma unroll
        for (int s = 0; s < 8; s++) {
            int jp0 = 8 * s + ti;
            uint32_t a0 = W2s[(mbase + g) * W2S_STRIDE + jp0];
            uint32_t a1 = W2s[(mbase + g + 8) * W2S_STRIDE + jp0];
            uint32_t a2 = W2s[(mbase + g) * W2S_STRIDE + jp0 + 4];
            uint32_t a3 = W2s[(mbase + g + 8) * W2S_STRIDE + jp0 + 4];
            #pragma unroll
            for (int j = 0; j < 16; j++) {
                uint32_t b0 = WpTs[(8 * j + g) * WPT_STRIDE + jp0];
                uint32_t b1v = WpTs[(8 * j + g) * WPT_STRIDE + jp0 + 4];
                mma_f16(facc[j], a0, a1, a2, a3, b0, b1v);
            }
        }
        // scatter into B2 pair layout (one-time)
        #pragma unroll
        for (int j = 0; j < 16; j++) {
            int n0 = 8 * j + 2 * ti;
            B2h[pair_half_idx(mbase + g, n0)]     = __float2half(facc[j][0]);
            B2h[pair_half_idx(mbase + g, n0 + 1)] = __float2half(facc[j][1]);
            B2h[pair_half_idx(mbase + g + 8, n0)]     = __float2half(facc[j][2]);
            B2h[pair_half_idx(mbase + g + 8, n0 + 1)] = __float2half(facc[j][3]);
        }
        // bias2p[n] = b2 @ Wp_top (f32, from gmem)
        if (tid < EDIM) {
            float ba = 0.f;
            #pragma unroll 8
            for (int j = 0; j < EDIM; j++) ba += __ldg(b2 + j) * __ldg(Wp + (size_t)j * EDIM + tid);
            b2ps[tid] = ba;
        }
    }
    __syncthreads();   // fold reads of staging done; A1/TAB regions reusable

    // --- fourier scratch: f[d][c], c<31  (A1 region scratch) ---
    {
        float* scr = (float*)(smem + OFF_A1);
        for (int t = tid; t < 960; t += NTHR) {
            int d = t / 15, i = t - d * 15;
            float coordf = (float)d * (float)(3.14 / 64.0);
            float fr = coordf * (float)(1 << i);
            scr[d * 32 + i]      = (float)sin((double)fr);
            scr[d * 32 + 15 + i] = (float)cos((double)fr);
            if (i == 0) scr[d * 32 + 30] = coordf;
        }
    }
    __syncthreads();

    // --- table[d][n] = bias2p[n] + fourier(d) @ Wp_bot  (overwrites WpT staging) ---
    {
        const float* scr = (const float*)(smem + OFF_A1);
        int n = tid & 127, dh = tid >> 7;    // dh in {0,1}
        float wpc[31];
        #pragma unroll
        for (int c = 0; c < 31; c++) wpc[c] = __ldg(Wp + (size_t)(EDIM + c) * EDIM + n);
        float bb = b2ps[n];
        #pragma unroll 4
        for (int u = 0; u < 32; u++) {
            int d = dh + 2 * u;
            float acc = bb;
            #pragma unroll
            for (int c = 0; c < 31; c++) acc += scr[d * 32 + c] * wpc[c];
            tabs[d * TAB_STRIDE + n] = acc;
        }
    }
    __syncthreads();   // scratch reads done; A1 region now the real A1 buffers

    // --- zero A1 K-pad words (kp 36..39) in both buffers, this warp's rows ---
    uint32_t* A1w0 = A1u + mbase * A1_STRIDE;
    uint32_t* A1w1 = A1u + (A1_BUF_BYTES / 4) + mbase * A1_STRIDE;
    for (int i = lid; i < 64; i += 32) {
        A1w0[(i >> 2) * A1_STRIDE + 36 + (i & 3)] = 0;
        A1w1[(i >> 2) * A1_STRIDE + 36 + (i & 3)] = 0;
    }

    // --- first tile gather (into buffer 0) ---
    uint32_t* Gdst0 = A1w0 + (lid >> 1) * A1_STRIDE + (lid & 1) * 18;
    uint32_t* Gdst1 = A1w1 + (lid >> 1) * A1_STRIDE + (lid & 1) * 18;
    {
        int m0p = blockIdx.x * TILE_M;
        int draw = __ldg(label + m0p + grow);
        int dcl = draw < 0 ? 0 : (draw > 63 ? 63 : draw);
        if ((lid & 1) == 0) {
            labels_s[grow] = draw;
            if (out_label) out_label[m0p + grow] = (float)draw;
        }
        const float* rec = cost + (size_t)((m0p + grow) >> 2) * (GGRP * DDISP);
        float gv[36];
        #pragma unroll
        for (int gi = 0; gi < 4; gi++) {
            const float* src = rec + (grp4 + gi) * DDISP;
            #pragma unroll
            for (int c = 0; c < 9; c++) {
                int ix = dcl - 4 + c;
                ix = ix < 0 ? 0 : (ix > 63 ? 63 : ix);
                gv[gi * 9 + c] = __ldg(src + ix);
            }
        }
        #pragma unroll
        for (int w = 0; w < 18; w++) Gdst0[w] = pack_h2(gv[2 * w], gv[2 * w + 1]);
    }
    __syncwarp();

    // ================= MAIN LOOP =================
    int cb = 0;
    for (int tile = blockIdx.x; tile < NTILES; tile += GRID_X) {
        const int m0 = tile * TILE_M;
        const int nxt = tile + GRID_X;
        const bool hn = nxt < NTILES;
        uint32_t* A1w = cb ? A1w1 : A1w0;
        uint32_t* Gdst = cb ? Gdst0 : Gdst1;   // commit into the OTHER buffer

        // prefetch next tile's label
        int draw = 0;
        if (hn) draw = __ldg(label + nxt * TILE_M + grow);

        // ---- GEMM1: m16 x n128, K=80 (5 k16 steps), B via LDS.64 pairs ----
        float acc1[16][4];
        #pragma unroll
        for (int j = 0; j < 16; j++)
            #pragma unroll
            for (int u = 0; u < 4; u++) acc1[j][u] = 0.f;

        #pragma unroll
        for (int s = 0; s < 5; s++) {
            int kp0 = 8 * s + ti;
            uint32_t a0 = A1w[g * A1_STRIDE + kp0];
            uint32_t a1 = A1w[(g + 8) * A1_STRIDE + kp0];
            uint32_t a2 = A1w[g * A1_STRIDE + kp0 + 4];
            uint32_t a3 = A1w[(g + 8) * A1_STRIDE + kp0 + 4];
            const uint2* bp = B1p + s * PAIR_S + ti * PAIR_TI + g;
            #pragma unroll
            for (int j = 0; j < 16; j++) {
                uint2 b = bp[8 * j];
                mma_f16(acc1[j], a0, a1, a2, a3, b.x, b.y);
            }
        }

        // ---- gelu(x+b1), repack C-frags as GEMM2 A-frags ----
        uint32_t ha[8][4];
        #pragma unroll
        for (int s = 0; s < 8; s++) {
            int j0 = 2 * s, j1 = 2 * s + 1;
            float2 bb0 = *(const float2*)(b1s + 8 * j0 + 2 * ti);
            float2 bb1 = *(const float2*)(b1s + 8 * j1 + 2 * ti);
            ha[s][0] = pack_h2(gelu_fast(acc1[j0][0] + bb0.x), gelu_fast(acc1[j0][1] + bb0.y));
            ha[s][1] = pack_h2(gelu_fast(acc1[j0][2] + bb0.x), gelu_fast(acc1[j0][3] + bb0.y));
            ha[s][2] = pack_h2(gelu_fast(acc1[j1][0] + bb1.x), gelu_fast(acc1[j1][1] + bb1.y));
            ha[s][3] = pack_h2(gelu_fast(acc1[j1][2] + bb1.x), gelu_fast(acc1[j1][3] + bb1.y));
        }

        // ---- issue next-tile gather loads ----
        float gv[36];
        if (hn) {
            int dcl = draw < 0 ? 0 : (draw > 63 ? 63 : draw);
            const float* rec = cost + (size_t)((nxt * TILE_M + grow) >> 2) * (GGRP * DDISP);
            #pragma unroll
            for (int gi = 0; gi < 4; gi++) {
                const float* src = rec + (grp4 + gi) * DDISP;
                #pragma unroll
                for (int c = 0; c < 9; c++) {
                    int ix = dcl - 4 + c;
                    ix = ix < 0 ? 0 : (ix > 63 ? 63 : ix);
                    gv[gi * 9 + c] = __ldg(src + ix);
                }
            }
        }

        // ---- GEMM2: A from registers, K=128 (8 k16 steps) ----
        float acc2[16][4];
        #pragma unroll
        for (int j = 0; j < 16; j++)
            #pragma unroll
            for (int u = 0; u < 4; u++) acc2[j][u] = 0.f;

        #pragma unroll
        for (int s = 0; s < 8; s++) {
            const uint2* bp = B2p + s * PAIR_S + ti * PAIR_TI + g;
            #pragma unroll
            for (int j = 0; j < 16; j++) {
                uint2 b = bp[8 * j];
                mma_f16(acc2[j], ha[s][0], ha[s][1], ha[s][2], ha[s][3], b.x, b.y);
            }
        }

        // ---- epilogue: out = acc2 + table[d] ----
        {
            int r0 = mbase + g, r1 = r0 + 8;
            int d0 = labels_s[cb * TILE_M + r0];
            int d1 = labels_s[cb * TILE_M + r1];
            d0 = d0 < 0 ? 0 : (d0 > 63 ? 63 : d0);
            d1 = d1 < 0 ? 0 : (d1 > 63 ? 63 : d1);
            const float* t0 = tabs + d0 * TAB_STRIDE + 2 * ti;
            const float* t1 = tabs + d1 * TAB_STRIDE + 2 * ti;
            float* o0 = out_embed + (size_t)(m0 + r0) * EDIM + 2 * ti;
            float* o1 = out_embed + (size_t)(m0 + r1) * EDIM + 2 * ti;
            #pragma unroll
            for (int j = 0; j < 16; j++) {
                float2 tv0 = *(const float2*)(t0 + 8 * j);
                float2 tv1 = *(const float2*)(t1 + 8 * j);
                float2 v0, v1;
                v0.x = acc2[j][0] + tv0.x;  v0.y = acc2[j][1] + tv0.y;
                v1.x = acc2[j][2] + tv1.x;  v1.y = acc2[j][3] + tv1.y;
                *(float2*)(o0 + 8 * j) = v0;
                *(float2*)(o1 + 8 * j) = v1;
            }
        }

        // ---- commit next-tile gather + labels (warp-private) ----
        if (hn) {
            #pragma unroll
            for (int w = 0; w < 18; w++) Gdst[w] = pack_h2(gv[2 * w], gv[2 * w + 1]);
            if ((lid & 1) == 0) {
                labels_s[(cb ^ 1) * TILE_M + grow] = draw;
                if (out_label) out_label[nxt * TILE_M + grow] = (float)draw;
            }
        }
        __syncwarp();
        cb ^= 1;
    }
}

// ---------------- launch ----------------
extern "C" void kernel_launch(void* const* d_in, const int* in_sizes, int n_in,
                              void* d_out, int out_size) {
    const float* cost  = (const float*)d_in[0];
    const int*   label = (const int*)d_in[1];
    // d_in[2] = context (unused: layers=[] passthrough)
    const float* W1 = (const float*)d_in[3];
    const float* b1 = (const float*)d_in[4];
    const float* W2 = (const float*)d_in[5];
    const float* b2 = (const float*)d_in[6];
    const float* Wp = (const float*)d_in[7];

    float* out = (float*)d_out;
    float* out_label = (out_size >= TOT_ELEMS) ? (out + EMB_ELEMS) : nullptr;

    cudaFuncSetAttribute(propagation_kernel,
                         cudaFuncAttributeMaxDynamicSharedMemorySize, SMEM_TOTAL);

    propagation_kernel<<<GRID_X, NTHR, SMEM_TOTAL>>>(cost, label, W1, b1, W2, b2, Wp,
                                                     out, out_label);
}